// round 8
// baseline (speedup 1.0000x reference)
#include <cuda_runtime.h>
#include <cuda_bf16.h>
#include <math.h>

// ---------------- problem constants ----------------
#define B   64
#define S   128
#define D   64
#define H   256
#define P   1024
#define VR  32000          // VOCAB * REPEAT
#define G4  1024           // 4*H
#define THRESH 0.64f

typedef unsigned long long ull;

// ---------------- device scratch (static, allowed) ----------------
__device__ float    g_xt  [2*S*B*D];        // transposed x: [(inp,s,b), d]
__device__ float    g_xg  [2*S*B*G4];       // xg buffer (layer0 then layer1)
__device__ float    g_hs  [2*S*B*H];        // layer0 hidden states
__device__ float    g_hbuf[2*2*B*H];        // h double buffer for scan
__device__ float    g_cat [B*2*H];          // concat(out1,out2) [64][512]
__device__ float    g_h1  [B*P];
__device__ float    g_h2  [B*P];
__device__ float    g_hbn [B*P];
__device__ int      g_cnt [B];
__device__ unsigned g_bar [8];

// ---------------- f32x2 packed helpers ----------------
__device__ __forceinline__ ull pk2(float lo, float hi) {
    ull r; asm("mov.b64 %0, {%1, %2};" : "=l"(r) : "f"(lo), "f"(hi)); return r;
}
__device__ __forceinline__ float2 upk2(ull v) {
    float2 f; asm("mov.b64 {%0, %1}, %2;" : "=f"(f.x), "=f"(f.y) : "l"(v)); return f;
}
__device__ __forceinline__ ull ffma2(ull a, ull b, ull c) {
    ull d; asm("fma.rn.f32x2 %0, %1, %2, %3;" : "=l"(d) : "l"(a), "l"(b), "l"(c)); return d;
}
__device__ __forceinline__ float fast_tanh(float x) {
    float r; asm("tanh.approx.f32 %0, %1;" : "=f"(r) : "f"(x)); return r;
}
__device__ __forceinline__ float sigf(float x) {
    return fmaf(fast_tanh(0.5f * x), 0.5f, 0.5f);
}

// ---------------- init / finalize ----------------
__global__ void init_kernel() {
    int t = threadIdx.x;
    if (t < 8)  g_bar[t] = 0u;
    if (t < B)  g_cnt[t] = 0;
}

__global__ void finalize_kernel(float* out_tail, int do_write) {
    int b = threadIdx.x;
    if (b < B && do_write) {
        int n = g_cnt[b];
        if (n < 1) n = 1;
        out_tail[b] = (float)n;
    }
}

// ---------------- x transpose: [B,S,D] -> [(inp,s,b),d] ----------------
__global__ void prep_x(const float* __restrict__ x1, const float* __restrict__ x2) {
    int idx = blockIdx.x * blockDim.x + threadIdx.x;
    if (idx >= 2*S*B*D) return;
    int d   = idx & 63;
    int b   = (idx >> 6) & 63;
    int s   = (idx >> 12) & 127;
    int inp = idx >> 19;
    const float* x = inp ? x2 : x1;
    g_xt[idx] = x[(b * S + s) * D + d];
}

// ---------------- generic SIMT GEMM (f32x2 packed):  C = epi(A @ W^T + bias) ----------------
// MODE 0: bias(+bias2); 1: exact GELU; 2: resid + relu; 3: relu + per-row count(v>THRESH)
template<int MODE>
__global__ void gemm_k(const float* __restrict__ A, const float* __restrict__ W,
                       const float* __restrict__ bias, const float* __restrict__ bias2,
                       const float* __restrict__ resid, float* __restrict__ C,
                       int M, int N, int K, int* __restrict__ cnt) {
    __shared__ float As[16][64];
    __shared__ float Bs[16][64];
    __shared__ int   scnt[64];

    const int t     = threadIdx.x;           // 256
    const int mBase = blockIdx.y * 64;
    const int nBase = blockIdx.x * 64;
    const int lr    = t >> 2;                // 0..63
    const int lk    = (t & 3) * 4;           // 0,4,8,12
    const int tm    = t >> 4;                // 0..15
    const int tn    = t & 15;                // 0..15

    if (MODE == 3 && t < 64) scnt[t] = 0;

    ull accP[2][4];                          // packed rows (2i,2i+1) x 4 cols
    #pragma unroll
    for (int i = 0; i < 2; i++)
        #pragma unroll
        for (int j = 0; j < 4; j++) accP[i][j] = 0ull;

    for (int kb = 0; kb < K; kb += 16) {
        __syncthreads();
        float4 av = *(const float4*)(A + (size_t)(mBase + lr) * K + kb + lk);
        float4 wv = *(const float4*)(W + (size_t)(nBase + lr) * K + kb + lk);
        As[lk + 0][lr] = av.x; As[lk + 1][lr] = av.y; As[lk + 2][lr] = av.z; As[lk + 3][lr] = av.w;
        Bs[lk + 0][lr] = wv.x; Bs[lk + 1][lr] = wv.y; Bs[lk + 2][lr] = wv.z; Bs[lk + 3][lr] = wv.w;
        __syncthreads();
        #pragma unroll
        for (int k = 0; k < 16; k++) {
            float4 a = *(const float4*)&As[k][tm * 4];
            float4 b = *(const float4*)&Bs[k][tn * 4];
            ull aP0 = pk2(a.x, a.y);
            ull aP1 = pk2(a.z, a.w);
            ull b0  = pk2(b.x, b.x);
            ull b1  = pk2(b.y, b.y);
            ull b2  = pk2(b.z, b.z);
            ull b3  = pk2(b.w, b.w);
            accP[0][0] = ffma2(aP0, b0, accP[0][0]);
            accP[0][1] = ffma2(aP0, b1, accP[0][1]);
            accP[0][2] = ffma2(aP0, b2, accP[0][2]);
            accP[0][3] = ffma2(aP0, b3, accP[0][3]);
            accP[1][0] = ffma2(aP1, b0, accP[1][0]);
            accP[1][1] = ffma2(aP1, b1, accP[1][1]);
            accP[1][2] = ffma2(aP1, b2, accP[1][2]);
            accP[1][3] = ffma2(aP1, b3, accP[1][3]);
        }
    }

    float acc[4][4];
    #pragma unroll
    for (int p = 0; p < 2; p++)
        #pragma unroll
        for (int j = 0; j < 4; j++) {
            float2 v = upk2(accP[p][j]);
            acc[2*p][j]   = v.x;
            acc[2*p+1][j] = v.y;
        }

    #pragma unroll
    for (int i = 0; i < 4; i++) {
        int r  = mBase + tm * 4 + i;
        int rc = 0;
        #pragma unroll
        for (int jj = 0; jj < 4; jj++) {
            int n = nBase + tn * 4 + jj;
            float v = acc[i][jj] + bias[n];
            if (bias2) v += bias2[n];
            if (MODE == 1) v = 0.5f * v * (1.f + erff(v * 0.70710678118654752f));
            if (MODE == 2) v = resid[(size_t)r * N + n] + fmaxf(v, 0.f);
            if (MODE == 3) { v = fmaxf(v, 0.f); if (v > THRESH) rc++; }
            C[(size_t)r * N + n] = v;
        }
        if (MODE == 3 && rc) atomicAdd(&scnt[tm * 4 + i], rc);
    }
    if (MODE == 3) {
        __syncthreads();
        if (t < 64 && scnt[t]) atomicAdd(&cnt[mBase + t], scnt[t]);
    }
}

// ---------------- persistent LSTM scan (f32x2 packed) ----------------
// grid: 128 CTAs = inp(2) x bchunk(4: 16 batch rows) x hchunk(16: 16 hidden units)
// block: 128 threads = btile(8: 2 batch rows each) x j(16)
// SMEM: w2[256][16][2] ull (gate-pair-packed Whh slice) + h_dup[256][16] ull (h duplicated pairs)
__global__ void lstm_scan(const float* __restrict__ xg, const float* __restrict__ Whh,
                          float* __restrict__ hs_out, float* __restrict__ cat_out) {
    extern __shared__ ull smem[];
    ull* w2    = smem;                 // [256*16*2]
    ull* h_dup = smem + 256 * 16 * 2;  // [256*16]

    const int t   = threadIdx.x;                  // 128
    const int bt  = t >> 4;                       // 0..7
    const int j   = t & 15;                       // 0..15
    const int bx  = blockIdx.x;                   // 0..127
    const int inp = bx >> 6;
    const int bc  = (bx >> 4) & 3;
    const int hc  = bx & 15;
    const int grp = bx >> 4;                      // 0..7 (inp*4+bc)
    const int jg  = hc * 16 + j;                  // global hidden idx
    const int bl0 = bt * 2;                       // local batch 0..15
    const int b0  = bc * 16 + bl0;                // global batch

    // pack Whh slice: w2[(k*16+j)*2] = (Wi,Wf), [+1] = (Wg,Wo) for hidden jg, input k
    for (int k = bt * 32; k < bt * 32 + 32; k++) {
        w2[(k * 16 + j) * 2 + 0] = pk2(Whh[(0 * H + jg) * H + k], Whh[(1 * H + jg) * H + k]);
        w2[(k * 16 + j) * 2 + 1] = pk2(Whh[(2 * H + jg) * H + k], Whh[(3 * H + jg) * H + k]);
    }
    for (int i = t; i < 256 * 16; i += 128) h_dup[i] = 0ull;
    __syncthreads();

    float c0 = 0.f, c1 = 0.f, sum0 = 0.f, sum1 = 0.f;
    float* hb_base = g_hbuf + inp * 2 * B * H;

    for (int s = 0; s < S; s++) {
        ull aif0 = 0ull, ago0 = 0ull, aif1 = 0ull, ago1 = 0ull;
        const ulonglong2* wv = (const ulonglong2*)w2;
        #pragma unroll 16
        for (int k = 0; k < H; k++) {
            ulonglong2 w = wv[k * 16 + j];     // .x=(Wi,Wf) .y=(Wg,Wo)
            ull hd0 = h_dup[k * 16 + bl0];
            ull hd1 = h_dup[k * 16 + bl0 + 1];
            aif0 = ffma2(w.x, hd0, aif0);
            ago0 = ffma2(w.y, hd0, ago0);
            aif1 = ffma2(w.x, hd1, aif1);
            ago1 = ffma2(w.y, hd1, ago1);
        }
        float2 vif0 = upk2(aif0), vgo0 = upk2(ago0);
        float2 vif1 = upk2(aif1), vgo1 = upk2(ago1);

        const float* xr = xg + ((size_t)(inp * S + s) * B + b0) * G4;
        float gi0 = vif0.x + xr[jg];
        float gf0 = vif0.y + xr[H + jg];
        float gg0 = vgo0.x + xr[2 * H + jg];
        float go0 = vgo0.y + xr[3 * H + jg];
        float gi1 = vif1.x + xr[G4 + jg];
        float gf1 = vif1.y + xr[G4 + H + jg];
        float gg1 = vgo1.x + xr[G4 + 2 * H + jg];
        float go1 = vgo1.y + xr[G4 + 3 * H + jg];

        c0 = sigf(gf0) * c0 + sigf(gi0) * fast_tanh(gg0);
        float h0 = sigf(go0) * fast_tanh(c0);
        c1 = sigf(gf1) * c1 + sigf(gi1) * fast_tanh(gg1);
        float h1 = sigf(go1) * fast_tanh(c1);

        float* hw = hb_base + (s & 1) * B * H;
        __stcg(&hw[(b0)     * H + jg], h0);
        __stcg(&hw[(b0 + 1) * H + jg], h1);

        if (hs_out) {
            hs_out[((size_t)(inp * S + s) * B + b0) * H + jg]     = h0;
            hs_out[((size_t)(inp * S + s) * B + b0) * H + H + jg] = h1;
        } else {
            sum0 += h0; sum1 += h1;
        }

        __threadfence();
        __syncthreads();
        if (t == 0) {
            atomicAdd(&g_bar[grp], 1u);
            unsigned target = 16u * (unsigned)(s + 1);
            while (*(volatile unsigned*)&g_bar[grp] < target) { }
            __threadfence();
        }
        __syncthreads();

        // reload this CTA's 16 batch rows of h (full H) from L2 into duplicated-pair layout
        const float4* hr = (const float4*)(hb_base + (s & 1) * B * H + (bc * 16) * H);
        #pragma unroll
        for (int q = 0; q < 8; q++) {
            int fidx = t + 128 * q;          // 0..1023
            int bl   = fidx & 15;            // local batch row
            int kq   = fidx >> 4;            // 0..63 (float4 index within row)
            float4 v = __ldcg(hr + bl * 64 + kq);
            int kb   = kq * 4;
            h_dup[(kb + 0) * 16 + bl] = pk2(v.x, v.x);
            h_dup[(kb + 1) * 16 + bl] = pk2(v.y, v.y);
            h_dup[(kb + 2) * 16 + bl] = pk2(v.z, v.z);
            h_dup[(kb + 3) * 16 + bl] = pk2(v.w, v.w);
        }
        __syncthreads();
    }

    if (cat_out) {
        cat_out[(b0)     * (2 * H) + inp * H + jg] = sum0;
        cat_out[(b0 + 1) * (2 * H) + inp * H + jg] = sum1;
    }
}

// ---------------- batchnorm over batch (training-mode stats) ----------------
__global__ void bn_kernel(const float* __restrict__ h, const float* __restrict__ gam,
                          const float* __restrict__ bet, float* __restrict__ out) {
    int c = blockIdx.x * blockDim.x + threadIdx.x;
    if (c >= P) return;
    float s = 0.f, s2 = 0.f;
    for (int r = 0; r < B; r++) {
        float v = h[r * P + c];
        s += v; s2 += v * v;
    }
    float mu  = s * (1.f / B);
    float var = s2 * (1.f / B) - mu * mu;
    float inv = rsqrtf(var + 1e-5f) * gam[c];
    float bb  = bet[c];
    for (int r = 0; r < B; r++) {
        out[r * P + c] = (h[r * P + c] - mu) * inv + bb;
    }
}

// ---------------- launcher ----------------
extern "C" void kernel_launch(void* const* d_in, const int* in_sizes, int n_in,
                              void* d_out, int out_size) {
    const float* x1    = (const float*)d_in[0];
    const float* x2    = (const float*)d_in[1];
    const float* Wih0  = (const float*)d_in[2];
    const float* Whh0  = (const float*)d_in[3];
    const float* bih0  = (const float*)d_in[4];
    const float* bhh0  = (const float*)d_in[5];
    const float* Wih1  = (const float*)d_in[6];
    const float* Whh1  = (const float*)d_in[7];
    const float* bih1  = (const float*)d_in[8];
    const float* bhh1  = (const float*)d_in[9];
    const float* fc1_w = (const float*)d_in[10];
    const float* fc1_b = (const float*)d_in[11];
    const float* fc2_w = (const float*)d_in[12];
    const float* fc2_b = (const float*)d_in[13];
    const float* fc3_w = (const float*)d_in[14];
    const float* fc3_b = (const float*)d_in[15];
    const float* bn_g  = (const float*)d_in[16];
    const float* bn_b  = (const float*)d_in[17];
    float* out = (float*)d_out;

    float *p_xt, *p_xg, *p_hs, *p_cat, *p_h1, *p_h2, *p_hbn;
    int   *p_cnt;
    cudaGetSymbolAddress((void**)&p_xt,  g_xt);
    cudaGetSymbolAddress((void**)&p_xg,  g_xg);
    cudaGetSymbolAddress((void**)&p_hs,  g_hs);
    cudaGetSymbolAddress((void**)&p_cat, g_cat);
    cudaGetSymbolAddress((void**)&p_h1,  g_h1);
    cudaGetSymbolAddress((void**)&p_h2,  g_h2);
    cudaGetSymbolAddress((void**)&p_hbn, g_hbn);
    cudaGetSymbolAddress((void**)&p_cnt, g_cnt);

    const int SCAN_SMEM = (256*16*2 + 256*16) * 8;   // 98304 bytes
    cudaFuncSetAttribute(lstm_scan, cudaFuncAttributeMaxDynamicSharedMemorySize, SCAN_SMEM);

    // 1) init barriers/counters
    init_kernel<<<1, 128>>>();

    // 2) transpose x into (inp,s,b,d)
    prep_x<<<(2*S*B*D + 255) / 256, 256>>>(x1, x2);

    // 3) xg0 = xT @ Wih0^T + (bih0 + bhh0)   [16384 x 1024], K=64
    gemm_k<0><<<dim3(G4/64, (2*S*B)/64), 256>>>(p_xt, Wih0, bih0, bhh0, nullptr, p_xg,
                                                2*S*B, G4, D, nullptr);

    // 4) layer-0 recurrence (writes hs)
    lstm_scan<<<128, 128, SCAN_SMEM>>>(p_xg, Whh0, p_hs, nullptr);

    // 5) reset barriers for second scan
    init_kernel<<<1, 128>>>();

    // 6) xg1 = hs @ Wih1^T + (bih1 + bhh1)   [16384 x 1024], K=256
    gemm_k<0><<<dim3(G4/64, (2*S*B)/64), 256>>>(p_hs, Wih1, bih1, bhh1, nullptr, p_xg,
                                                2*S*B, G4, H, nullptr);

    // 7) layer-1 recurrence (accumulates time-sum directly into concat layout)
    lstm_scan<<<128, 128, SCAN_SMEM>>>(p_xg, Whh1, nullptr, p_cat);

    // 8) fc1 + exact GELU: [64 x 1024], K=512
    gemm_k<1><<<dim3(P/64, 1), 256>>>(p_cat, fc1_w, fc1_b, nullptr, nullptr, p_h1,
                                      B, P, 2*H, nullptr);

    // 9) fc2 + relu + residual: [64 x 1024], K=1024
    gemm_k<2><<<dim3(P/64, 1), 256>>>(p_h1, fc2_w, fc2_b, nullptr, p_h1, p_h2,
                                      B, P, P, nullptr);

    // 10) batchnorm (batch statistics)
    bn_kernel<<<(P + 255) / 256, 256>>>(p_h2, bn_g, bn_b, p_hbn);

    // 11) fc3 + relu + threshold count -> scores straight into d_out
    gemm_k<3><<<dim3(VR/64, 1), 256>>>(p_hbn, fc3_w, fc3_b, nullptr, nullptr, out,
                                       B, VR, P, p_cnt);

    // 12) num_select (as float) appended after scores, if the output has room
    int has_tail = (out_size >= B * VR + B) ? 1 : 0;
    finalize_kernel<<<1, 64>>>(out + (size_t)B * VR, has_tail);
}

// round 11
// speedup vs baseline: 1.6641x; 1.6641x over previous
#include <cuda_runtime.h>
#include <cuda_bf16.h>
#include <math.h>

#define B   64
#define S   128
#define D   64
#define H   256
#define P   1024
#define VR  32000
#define G4  1024
#define THRESH 0.64f

typedef unsigned long long ull;

__device__ float    g_xt  [2*S*B*D];
__device__ float    g_xg  [2*S*B*G4];
__device__ float    g_hs  [2*S*B*H];
__device__ float    g_hbuf[2*2*B*H];
__device__ float    g_cat [B*2*H];
__device__ float    g_h1  [B*P];
__device__ float    g_h2  [B*P];
__device__ float    g_hbn [B*P];
__device__ int      g_cnt [B];
__device__ unsigned g_bar [16];

__device__ __forceinline__ ull pk2(float lo, float hi) {
    ull r; asm("mov.b64 %0, {%1, %2};" : "=l"(r) : "f"(lo), "f"(hi)); return r;
}
__device__ __forceinline__ float2 upk2(ull v) {
    float2 f; asm("mov.b64 {%0, %1}, %2;" : "=f"(f.x), "=f"(f.y) : "l"(v)); return f;
}
__device__ __forceinline__ ull ffma2(ull a, ull b, ull c) {
    ull d; asm("fma.rn.f32x2 %0, %1, %2, %3;" : "=l"(d) : "l"(a), "l"(b), "l"(c)); return d;
}
__device__ __forceinline__ ull add2(ull a, ull b) {
    ull d; asm("add.rn.f32x2 %0, %1, %2;" : "=l"(d) : "l"(a), "l"(b)); return d;
}
__device__ __forceinline__ float fast_tanh(float x) {
    float r; asm("tanh.approx.f32 %0, %1;" : "=f"(r) : "f"(x)); return r;
}
__device__ __forceinline__ float sigf(float x) {
    return fmaf(fast_tanh(0.5f * x), 0.5f, 0.5f);
}

__global__ void init_kernel() {
    int t = threadIdx.x;
    if (t < 16) g_bar[t] = 0u;
    if (t < B)  g_cnt[t] = 0;
}

__global__ void finalize_kernel(float* out_tail, int do_write) {
    int b = threadIdx.x;
    if (b < B && do_write) {
        int n = g_cnt[b];
        if (n < 1) n = 1;
        out_tail[b] = (float)n;
    }
}

__global__ void prep_x(const float* __restrict__ x1, const float* __restrict__ x2) {
    int idx = blockIdx.x * blockDim.x + threadIdx.x;
    if (idx >= 2*S*B*D) return;
    int d   = idx & 63;
    int b   = (idx >> 6) & 63;
    int s   = (idx >> 12) & 127;
    int inp = idx >> 19;
    const float* x = inp ? x2 : x1;
    g_xt[idx] = x[(b * S + s) * D + d];
}

// MODE 0: bias(+bias2); 1: exact GELU; 2: resid + relu; 3: relu + count(v>THRESH)
template<int MODE>
__global__ void gemm_k(const float* __restrict__ A, const float* __restrict__ W,
                       const float* __restrict__ bias, const float* __restrict__ bias2,
                       const float* __restrict__ resid, float* __restrict__ C,
                       int M, int N, int K, int* __restrict__ cnt) {
    __shared__ float As[16][64];
    __shared__ float Bs[16][64];
    __shared__ int   scnt[64];

    const int t     = threadIdx.x;
    const int mBase = blockIdx.y * 64;
    const int nBase = blockIdx.x * 64;
    const int lr    = t >> 2;
    const int lk    = (t & 3) * 4;
    const int tm    = t >> 4;
    const int tn    = t & 15;

    if (MODE == 3 && t < 64) scnt[t] = 0;

    ull accP[2][4];
    #pragma unroll
    for (int i = 0; i < 2; i++)
        #pragma unroll
        for (int j = 0; j < 4; j++) accP[i][j] = 0ull;

    for (int kb = 0; kb < K; kb += 16) {
        __syncthreads();
        float4 av = *(const float4*)(A + (size_t)(mBase + lr) * K + kb + lk);
        float4 wv = *(const float4*)(W + (size_t)(nBase + lr) * K + kb + lk);
        As[lk + 0][lr] = av.x; As[lk + 1][lr] = av.y; As[lk + 2][lr] = av.z; As[lk + 3][lr] = av.w;
        Bs[lk + 0][lr] = wv.x; Bs[lk + 1][lr] = wv.y; Bs[lk + 2][lr] = wv.z; Bs[lk + 3][lr] = wv.w;
        __syncthreads();
        #pragma unroll
        for (int k = 0; k < 16; k++) {
            float4 a = *(const float4*)&As[k][tm * 4];
            float4 b = *(const float4*)&Bs[k][tn * 4];
            ull aP0 = pk2(a.x, a.y);
            ull aP1 = pk2(a.z, a.w);
            ull b0  = pk2(b.x, b.x);
            ull b1  = pk2(b.y, b.y);
            ull b2  = pk2(b.z, b.z);
            ull b3  = pk2(b.w, b.w);
            accP[0][0] = ffma2(aP0, b0, accP[0][0]);
            accP[0][1] = ffma2(aP0, b1, accP[0][1]);
            accP[0][2] = ffma2(aP0, b2, accP[0][2]);
            accP[0][3] = ffma2(aP0, b3, accP[0][3]);
            accP[1][0] = ffma2(aP1, b0, accP[1][0]);
            accP[1][1] = ffma2(aP1, b1, accP[1][1]);
            accP[1][2] = ffma2(aP1, b2, accP[1][2]);
            accP[1][3] = ffma2(aP1, b3, accP[1][3]);
        }
    }

    float acc[4][4];
    #pragma unroll
    for (int p = 0; p < 2; p++)
        #pragma unroll
        for (int j = 0; j < 4; j++) {
            float2 v = upk2(accP[p][j]);
            acc[2*p][j]   = v.x;
            acc[2*p+1][j] = v.y;
        }

    #pragma unroll
    for (int i = 0; i < 4; i++) {
        int r  = mBase + tm * 4 + i;
        int rc = 0;
        #pragma unroll
        for (int jj = 0; jj < 4; jj++) {
            int n = nBase + tn * 4 + jj;
            float v = acc[i][jj] + bias[n];
            if (bias2) v += bias2[n];
            if (MODE == 1) v = 0.5f * v * (1.f + erff(v * 0.70710678118654752f));
            if (MODE == 2) v = resid[(size_t)r * N + n] + fmaxf(v, 0.f);
            if (MODE == 3) { v = fmaxf(v, 0.f); if (v > THRESH) rc++; }
            C[(size_t)r * N + n] = v;
        }
        if (MODE == 3 && rc) atomicAdd(&scnt[tm * 4 + i], rc);
    }
    if (MODE == 3) {
        __syncthreads();
        if (t < 64 && scnt[t]) atomicAdd(&cnt[mBase + t], scnt[t]);
    }
}

// ---------------- persistent LSTM scan v2 (k-paired f32x2, 2 CTAs/SM) ----------------
// grid 256 = inp(2) x bchunk(8 rows of 8) x hchunk(16 j); block 256 = kq(8) x gh(2) x jj(16)
#define SCAN2_WK_BYTES   65536
#define SCAN2_HD_BYTES   10240          // 128 k2 * (8 rows * 8B + 16B pad)
#define SCAN2_SCR_BYTES  17408          // 128 slots * 17 ull
#define SCAN2_SMEM (SCAN2_WK_BYTES + SCAN2_HD_BYTES + SCAN2_SCR_BYTES)

__global__ __launch_bounds__(256, 2)
void lstm_scan2(const float* __restrict__ xg, const float* __restrict__ Whh,
                float* __restrict__ hs_out, float* __restrict__ cat_out) {
    extern __shared__ unsigned char smraw[];
    ull*           wk  = (ull*)smraw;                                  // [(k2*16+jj)*4+g]
    unsigned char* hd  = smraw + SCAN2_WK_BYTES;                       // [k2]{8 float2 + pad}
    ull*           scr = (ull*)(smraw + SCAN2_WK_BYTES + SCAN2_HD_BYTES);

    const int t    = threadIdx.x;
    const int kq   = t >> 5;                      // 0..7
    const int gh   = (t >> 4) & 1;                // 0:(i,f)  1:(g,o)
    const int jj   = t & 15;
    const int lane = t & 31;
    const int bx   = blockIdx.x;
    const int inp  = bx >> 7;
    const int bc   = (bx >> 4) & 7;
    const int hc   = bx & 15;
    const int grp  = bx >> 4;                     // 0..15
    const int b0   = bc * 8;

    const int erow = t >> 4;                      // epilogue: 0..7 (t<128)
    const int ejj  = t & 15;
    const int jge  = hc * 16 + ejj;

    // weights: wk[(k2*16+jj)*4+g] = (Whh[g*H+jg][2k2], [2k2+1])
    for (int i = t; i < 128 * 16 * 4; i += 256) {
        int k2  = i >> 6;
        int jj2 = (i >> 2) & 15;
        int g   = i & 3;
        wk[i] = *(const ull*)(Whh + ((size_t)(g * H + hc * 16 + jj2)) * H + 2 * k2);
    }
    for (int i = t; i < SCAN2_HD_BYTES / 8; i += 256) ((ull*)hd)[i] = 0ull;
    __syncthreads();

    float c_st = 0.f, sumh = 0.f;

    for (int s = 0; s < S; s++) {
        float xv0 = 0.f, xv1 = 0.f, xv2 = 0.f, xv3 = 0.f;
        if (t < 128) {
            const float* xr = xg + ((size_t)((inp * S + s) * B) + b0 + erow) * G4;
            xv0 = __ldcg(xr + jge);
            xv1 = __ldcg(xr + H + jge);
            xv2 = __ldcg(xr + 2 * H + jge);
            xv3 = __ldcg(xr + 3 * H + jge);
        }

        ull accA[8], accB[8];
        #pragma unroll
        for (int r = 0; r < 8; r++) { accA[r] = 0ull; accB[r] = 0ull; }

        const int k2base = kq * 16;
        #pragma unroll 4
        for (int kk = 0; kk < 16; kk++) {
            int k2 = k2base + kk;
            ulonglong2 wv = *(const ulonglong2*)(wk + ((k2 * 16 + jj) * 4 + 2 * gh));
            const ulonglong2* hp = (const ulonglong2*)(hd + k2 * 80);
            ulonglong2 h01 = hp[0];
            ulonglong2 h23 = hp[1];
            ulonglong2 h45 = hp[2];
            ulonglong2 h67 = hp[3];
            accA[0] = ffma2(wv.x, h01.x, accA[0]); accB[0] = ffma2(wv.y, h01.x, accB[0]);
            accA[1] = ffma2(wv.x, h01.y, accA[1]); accB[1] = ffma2(wv.y, h01.y, accB[1]);
            accA[2] = ffma2(wv.x, h23.x, accA[2]); accB[2] = ffma2(wv.y, h23.x, accB[2]);
            accA[3] = ffma2(wv.x, h23.y, accA[3]); accB[3] = ffma2(wv.y, h23.y, accB[3]);
            accA[4] = ffma2(wv.x, h45.x, accA[4]); accB[4] = ffma2(wv.y, h45.x, accB[4]);
            accA[5] = ffma2(wv.x, h45.y, accA[5]); accB[5] = ffma2(wv.y, h45.y, accB[5]);
            accA[6] = ffma2(wv.x, h67.x, accA[6]); accB[6] = ffma2(wv.y, h67.x, accB[6]);
            accA[7] = ffma2(wv.x, h67.y, accA[7]); accB[7] = ffma2(wv.y, h67.y, accB[7]);
        }

        // reduce 8 kq chunks -> 2 phases
        if (kq >= 4) {
            ull* sp = scr + ((kq - 4) * 32 + lane) * 17;
            #pragma unroll
            for (int r = 0; r < 8; r++) { sp[r] = accA[r]; sp[8 + r] = accB[r]; }
        }
        __syncthreads();
        if (kq < 4) {
            ull* sp = scr + (kq * 32 + lane) * 17;
            #pragma unroll
            for (int r = 0; r < 8; r++) {
                accA[r] = add2(accA[r], sp[r]);
                accB[r] = add2(accB[r], sp[8 + r]);
            }
            #pragma unroll
            for (int r = 0; r < 8; r++) { sp[r] = accA[r]; sp[8 + r] = accB[r]; }
        }
        __syncthreads();

        if (t < 128) {
            ull si = 0ull, sf = 0ull, sg = 0ull, so = 0ull;
            #pragma unroll
            for (int q = 0; q < 4; q++) {
                const ull* sp0 = scr + (q * 32 + ejj) * 17;       // gh=0: gates i,f
                const ull* sp1 = scr + (q * 32 + 16 + ejj) * 17;  // gh=1: gates g,o
                si = add2(si, sp0[erow]);
                sf = add2(sf, sp0[8 + erow]);
                sg = add2(sg, sp1[erow]);
                so = add2(so, sp1[8 + erow]);
            }
            float2 vi = upk2(si), vf = upk2(sf), vg = upk2(sg), vo = upk2(so);
            float gi = vi.x + vi.y + xv0;
            float gf = vf.x + vf.y + xv1;
            float gg = vg.x + vg.y + xv2;
            float go = vo.x + vo.y + xv3;

            c_st = sigf(gf) * c_st + sigf(gi) * fast_tanh(gg);
            float hval = sigf(go) * fast_tanh(c_st);

            __stcg(g_hbuf + ((size_t)((inp * 2 + (s & 1)) * B) + b0 + erow) * H + jge, hval);

            if (hs_out) hs_out[((size_t)((inp * S + s) * B) + b0 + erow) * H + jge] = hval;
            else        sumh += hval;
        }
        __threadfence();
        __syncthreads();
        if (t == 0) {
            atomicAdd(&g_bar[grp], 1u);
            unsigned tgt = 16u * (unsigned)(s + 1);
            while (*(volatile unsigned*)&g_bar[grp] < tgt) { }
            __threadfence();
        }
        __syncthreads();

        // reload 8 rows x 256 h from L2 into k-paired layout
        const float* hb = g_hbuf + ((size_t)((inp * 2 + (s & 1)) * B) + b0) * H;
        #pragma unroll
        for (int q = 0; q < 2; q++) {
            int f  = q * 256 + t;          // 0..511
            int r  = f >> 6;
            int q4 = f & 63;
            float4 v = __ldcg((const float4*)(hb + r * H) + q4);
            *(ull*)(hd + (2 * q4    ) * 80 + r * 8) = pk2(v.x, v.y);
            *(ull*)(hd + (2 * q4 + 1) * 80 + r * 8) = pk2(v.z, v.w);
        }
        __syncthreads();
    }

    if (cat_out && t < 128)
        cat_out[(b0 + erow) * (2 * H) + inp * H + jge] = sumh;
}

__global__ void bn_kernel(const float* __restrict__ h, const float* __restrict__ gam,
                          const float* __restrict__ bet, float* __restrict__ out) {
    int c = blockIdx.x * blockDim.x + threadIdx.x;
    if (c >= P) return;
    float s = 0.f, s2 = 0.f;
    for (int r = 0; r < B; r++) {
        float v = h[r * P + c];
        s += v; s2 += v * v;
    }
    float mu  = s * (1.f / B);
    float var = s2 * (1.f / B) - mu * mu;
    float inv = rsqrtf(var + 1e-5f) * gam[c];
    float bb  = bet[c];
    for (int r = 0; r < B; r++) {
        out[r * P + c] = (h[r * P + c] - mu) * inv + bb;
    }
}

extern "C" void kernel_launch(void* const* d_in, const int* in_sizes, int n_in,
                              void* d_out, int out_size) {
    const float* x1    = (const float*)d_in[0];
    const float* x2    = (const float*)d_in[1];
    const float* Wih0  = (const float*)d_in[2];
    const float* Whh0  = (const float*)d_in[3];
    const float* bih0  = (const float*)d_in[4];
    const float* bhh0  = (const float*)d_in[5];
    const float* Wih1  = (const float*)d_in[6];
    const float* Whh1  = (const float*)d_in[7];
    const float* bih1  = (const float*)d_in[8];
    const float* bhh1  = (const float*)d_in[9];
    const float* fc1_w = (const float*)d_in[10];
    const float* fc1_b = (const float*)d_in[11];
    const float* fc2_w = (const float*)d_in[12];
    const float* fc2_b = (const float*)d_in[13];
    const float* fc3_w = (const float*)d_in[14];
    const float* fc3_b = (const float*)d_in[15];
    const float* bn_g  = (const float*)d_in[16];
    const float* bn_b  = (const float*)d_in[17];
    float* out = (float*)d_out;

    float *p_xt, *p_xg, *p_hs, *p_cat, *p_h1, *p_h2, *p_hbn;
    int   *p_cnt;
    cudaGetSymbolAddress((void**)&p_xt,  g_xt);
    cudaGetSymbolAddress((void**)&p_xg,  g_xg);
    cudaGetSymbolAddress((void**)&p_hs,  g_hs);
    cudaGetSymbolAddress((void**)&p_cat, g_cat);
    cudaGetSymbolAddress((void**)&p_h1,  g_h1);
    cudaGetSymbolAddress((void**)&p_h2,  g_h2);
    cudaGetSymbolAddress((void**)&p_hbn, g_hbn);
    cudaGetSymbolAddress((void**)&p_cnt, g_cnt);

    cudaFuncSetAttribute(lstm_scan2, cudaFuncAttributeMaxDynamicSharedMemorySize, SCAN2_SMEM);

    init_kernel<<<1, 128>>>();
    prep_x<<<(2*S*B*D + 255) / 256, 256>>>(x1, x2);

    // xg0 = xT @ Wih0^T + (bih0+bhh0)
    gemm_k<0><<<dim3(G4/64, (2*S*B)/64), 256>>>(p_xt, Wih0, bih0, bhh0, nullptr, p_xg,
                                                2*S*B, G4, D, nullptr);
    // layer-0 recurrence
    lstm_scan2<<<256, 256, SCAN2_SMEM>>>(p_xg, Whh0, p_hs, nullptr);

    init_kernel<<<1, 128>>>();

    // xg1 = hs @ Wih1^T + (bih1+bhh1)
    gemm_k<0><<<dim3(G4/64, (2*S*B)/64), 256>>>(p_hs, Wih1, bih1, bhh1, nullptr, p_xg,
                                                2*S*B, G4, H, nullptr);
    // layer-1 recurrence (time-sum into concat)
    lstm_scan2<<<256, 256, SCAN2_SMEM>>>(p_xg, Whh1, nullptr, p_cat);

    // fc1 + GELU
    gemm_k<1><<<dim3(P/64, 1), 256>>>(p_cat, fc1_w, fc1_b, nullptr, nullptr, p_h1,
                                      B, P, 2*H, nullptr);
    // fc2 + relu + residual
    gemm_k<2><<<dim3(P/64, 1), 256>>>(p_h1, fc2_w, fc2_b, nullptr, p_h1, p_h2,
                                      B, P, P, nullptr);
    // batchnorm
    bn_kernel<<<(P + 255) / 256, 256>>>(p_h2, bn_g, bn_b, p_hbn);
    // fc3 + relu + count
    gemm_k<3><<<dim3(VR/64, 1), 256>>>(p_hbn, fc3_w, fc3_b, nullptr, nullptr, out,
                                       B, VR, P, p_cnt);

    int has_tail = (out_size >= B * VR + B) ? 1 : 0;
    finalize_kernel<<<1, 64>>>(out + (size_t)B * VR, has_tail);
}